// round 14
// baseline (speedup 1.0000x reference)
#include <cuda_runtime.h>
#include <cuda_bf16.h>
#include <cstdint>

// Problem constants
#define SQ 512
#define BB 32
#define HH 1024
#define GG 4096
#define LL 3
#define MM (SQ*BB)
#define NBLK 128

typedef unsigned long long ull;

// ------------------------- scratch (device globals) --------------------------
__device__ float g_seqA[(size_t)MM * HH];
__device__ float g_seqB[(size_t)MM * HH];
__device__ float g_seqC[(size_t)MM * HH];
__device__ float g_G[(size_t)MM * GG];
__device__ float g_hT[LL * BB * HH];
__device__ float g_cT[LL * BB * HH];
__device__ unsigned g_flags[NBLK];
__device__ __nv_bfloat16 g_Ahi[(size_t)MM * HH];
__device__ __nv_bfloat16 g_Alo[(size_t)MM * HH];
__device__ __nv_bfloat16 g_Whi[(size_t)GG * HH];
__device__ __nv_bfloat16 g_Wlo[(size_t)GG * HH];

// ------------------------- grid barrier (per-thread flag poll) ---------------
// Threads 0..127 each own one flag: single acquire load per poll, detect
// latency ~ one L2 round trip after the last release. Other threads wait at
// the closing __syncthreads.
__device__ __forceinline__ void grid_barrier(unsigned target) {
    __syncthreads();
    const int tid = threadIdx.x;
    if (tid == 0) {
        asm volatile("st.release.gpu.global.u32 [%0], %1;"
                     :: "l"(&g_flags[blockIdx.x]), "r"(target) : "memory");
    }
    if (tid < NBLK) {
        const unsigned* f = g_flags + tid;
        unsigned v;
        do {
            asm volatile("ld.acquire.gpu.global.u32 %0, [%1];" : "=r"(v) : "l"(f));
        } while (v < target);
    }
    __syncthreads();
}

__global__ void reset_flags_kernel() {
    if (threadIdx.x < NBLK) g_flags[threadIdx.x] = 0u;
}

// ------------------------- embedding gather ----------------------------------
__global__ void gather_kernel(const int* __restrict__ x,
                              const float* __restrict__ emb,
                              float* __restrict__ out) {
    const int total = MM * (HH / 4);
    for (int i = blockIdx.x * blockDim.x + threadIdx.x; i < total;
         i += gridDim.x * blockDim.x) {
        int row = i >> 8;
        int col = i & 255;
        int tok = __ldg(x + row);
        float4 v = __ldg(((const float4*)(emb + (size_t)tok * HH)) + col);
        ((float4*)out)[i] = v;
    }
}

// ------------------------- fp32 -> bf16 hi/lo split ---------------------------
__global__ void cvt_kernel(const float* __restrict__ in,
                           __nv_bfloat16* __restrict__ hi,
                           __nv_bfloat16* __restrict__ lo, int n4) {
    for (int i = blockIdx.x * blockDim.x + threadIdx.x; i < n4;
         i += gridDim.x * blockDim.x) {
        float4 v = __ldcg(((const float4*)in) + i);
        __nv_bfloat16 h0 = __float2bfloat16(v.x);
        __nv_bfloat16 h1 = __float2bfloat16(v.y);
        __nv_bfloat16 h2 = __float2bfloat16(v.z);
        __nv_bfloat16 h3 = __float2bfloat16(v.w);
        __nv_bfloat16 l0 = __float2bfloat16(v.x - __bfloat162float(h0));
        __nv_bfloat16 l1 = __float2bfloat16(v.y - __bfloat162float(h1));
        __nv_bfloat16 l2 = __float2bfloat16(v.z - __bfloat162float(h2));
        __nv_bfloat16 l3 = __float2bfloat16(v.w - __bfloat162float(h3));
        ushort4 hp, lp;
        hp.x = *(unsigned short*)&h0; hp.y = *(unsigned short*)&h1;
        hp.z = *(unsigned short*)&h2; hp.w = *(unsigned short*)&h3;
        lp.x = *(unsigned short*)&l0; lp.y = *(unsigned short*)&l1;
        lp.z = *(unsigned short*)&l2; lp.w = *(unsigned short*)&l3;
        ((ushort4*)hi)[i] = hp;
        ((ushort4*)lo)[i] = lp;
    }
}

// ------------------------- mma.sync helpers -----------------------------------
__device__ __forceinline__ uint32_t smem_u32(const void* p) {
    uint32_t a;
    asm("{ .reg .u64 t; cvta.to.shared.u64 t, %1; cvt.u32.u64 %0, t; }"
        : "=r"(a) : "l"(p));
    return a;
}
__device__ __forceinline__ void ldsm_x4(uint32_t* r, uint32_t addr) {
    asm volatile("ldmatrix.sync.aligned.m8n8.x4.shared.b16 {%0,%1,%2,%3}, [%4];"
                 : "=r"(r[0]), "=r"(r[1]), "=r"(r[2]), "=r"(r[3]) : "r"(addr));
}
__device__ __forceinline__ void ldsm_x2(uint32_t* r, uint32_t addr) {
    asm volatile("ldmatrix.sync.aligned.m8n8.x2.shared.b16 {%0,%1}, [%2];"
                 : "=r"(r[0]), "=r"(r[1]) : "r"(addr));
}
__device__ __forceinline__ void mma_bf16(float* d, const uint32_t* a,
                                         const uint32_t* b) {
    asm volatile(
        "mma.sync.aligned.m16n8k16.row.col.f32.bf16.bf16.f32 "
        "{%0,%1,%2,%3}, {%4,%5,%6,%7}, {%8,%9}, {%0,%1,%2,%3};"
        : "+f"(d[0]), "+f"(d[1]), "+f"(d[2]), "+f"(d[3])
        : "r"(a[0]), "r"(a[1]), "r"(a[2]), "r"(a[3]), "r"(b[0]), "r"(b[1]));
}
__device__ __forceinline__ void cp16(uint32_t smaddr, const void* gaddr) {
    asm volatile("cp.async.cg.shared.global [%0], [%1], 16;"
                 :: "r"(smaddr), "l"(gaddr));
}
__device__ __forceinline__ uint32_t pack_bf2(float a, float b) {
    __nv_bfloat16 x = __float2bfloat16(a);
    __nv_bfloat16 y = __float2bfloat16(b);
    return (uint32_t)(*(unsigned short*)&x) | ((uint32_t)(*(unsigned short*)&y) << 16);
}

// ------------------------- tensor-core input GEMM (R10 verbatim) --------------
#define GP 40
__global__ __launch_bounds__(256, 2) void igemm_mma_kernel(
    const __nv_bfloat16* __restrict__ Ahi,
    const __nv_bfloat16* __restrict__ Alo,
    const __nv_bfloat16* __restrict__ Whi,
    const __nv_bfloat16* __restrict__ Wlo,
    const float* __restrict__ bias,
    float* __restrict__ C) {
    __shared__ __align__(16) __nv_bfloat16 sAhi[128 * GP];
    __shared__ __align__(16) __nv_bfloat16 sAlo[128 * GP];
    __shared__ __align__(16) __nv_bfloat16 sWhi[128 * GP];
    __shared__ __align__(16) __nv_bfloat16 sWlo[128 * GP];

    const int tid = threadIdx.x;
    const int wid = tid >> 5;
    const int lane = tid & 31;
    const int bm = blockIdx.y * 128;
    const int bn = blockIdx.x * 128;
    const int wm = wid & 3;
    const int wn = wid >> 2;

    float acc[2][8][4];
#pragma unroll
    for (int mt = 0; mt < 2; ++mt)
#pragma unroll
        for (int nt = 0; nt < 8; ++nt)
#pragma unroll
            for (int q = 0; q < 4; ++q) acc[mt][nt][q] = 0.f;

    const int lrow0 = tid >> 2;
    const int lq = tid & 3;
    const int l8 = lane & 7;
    const int asub = lane >> 3;
    const int arow = (asub & 1) * 8 + l8;
    const int akoff = (asub >> 1) * 8;
    const int bkoff = ((lane >> 3) & 1) * 8;

    const uint32_t sAhiB = smem_u32(sAhi);
    const uint32_t sAloB = smem_u32(sAlo);
    const uint32_t sWhiB = smem_u32(sWhi);
    const uint32_t sWloB = smem_u32(sWlo);

    for (int c = 0; c < 32; ++c) {
        if (c) __syncthreads();
        const int k0 = c * 32;
#pragma unroll
        for (int j = 0; j < 2; ++j) {
            const int row = lrow0 + j * 64;
            const uint32_t so = (uint32_t)(row * GP + lq * 8) * 2;
            const size_t ga = (size_t)(bm + row) * HH + k0 + lq * 8;
            const size_t gw = (size_t)(bn + row) * HH + k0 + lq * 8;
            cp16(sAhiB + so, Ahi + ga);
            cp16(sAloB + so, Alo + ga);
            cp16(sWhiB + so, Whi + gw);
            cp16(sWloB + so, Wlo + gw);
        }
        asm volatile("cp.async.commit_group;");
        asm volatile("cp.async.wait_group 0;" ::: "memory");
        __syncthreads();
#pragma unroll
        for (int term = 0; term < 3; ++term) {
            const uint32_t Asb = (term == 2) ? sAloB : sAhiB;
            const uint32_t Wsb = (term == 1) ? sWloB : sWhiB;
#pragma unroll
            for (int ks = 0; ks < 2; ++ks) {
                uint32_t a[2][4];
#pragma unroll
                for (int mt = 0; mt < 2; ++mt) {
                    const uint32_t aaddr = Asb
                        + ((uint32_t)((wm * 32 + mt * 16 + arow) * GP
                                      + ks * 16 + akoff)) * 2;
                    ldsm_x4(a[mt], aaddr);
                }
#pragma unroll
                for (int nt = 0; nt < 8; ++nt) {
                    uint32_t b[2];
                    const uint32_t baddr = Wsb
                        + ((uint32_t)((wn * 64 + nt * 8 + l8) * GP
                                      + ks * 16 + bkoff)) * 2;
                    ldsm_x2(b, baddr);
                    mma_bf16(acc[0][nt], a[0], b);
                    mma_bf16(acc[1][nt], a[1], b);
                }
            }
        }
    }

    const int g = lane >> 2;
    const int t2 = (lane & 3) * 2;
#pragma unroll
    for (int nt = 0; nt < 8; ++nt) {
        const int n = bn + wn * 64 + nt * 8 + t2;
        const float2 bv = *(const float2*)(bias + n);
#pragma unroll
        for (int mt = 0; mt < 2; ++mt) {
            const int m0 = bm + wm * 32 + mt * 16 + g;
            float2 o0, o1;
            o0.x = acc[mt][nt][0] + bv.x;
            o0.y = acc[mt][nt][1] + bv.y;
            o1.x = acc[mt][nt][2] + bv.x;
            o1.y = acc[mt][nt][3] + bv.y;
            *(float2*)(C + (size_t)m0 * GG + n) = o0;
            *(float2*)(C + (size_t)(m0 + 8) * GG + n) = o1;
        }
    }
}

// ------------------------- tensor-core persistent recurrence (R10 verbatim) ---
#define GPW 1032
#define HP2 264
#define OFF_WLO 66048
#define OFF_HB  132096
#define HBUF_SZ 16896
#define RECUR_SMEM 199680
__global__ __launch_bounds__(512, 1) void recur_mma_kernel(
    const float* __restrict__ Gin,   // [SQ*BB][GG] natural
    const float* __restrict__ Whh,   // [GG, HH]
    const float* __restrict__ h0,
    const float* __restrict__ c0,
    float* __restrict__ out,         // [SQ,BB,HH]
    float* __restrict__ hT,
    float* __restrict__ cT,
    unsigned flag_base) {
    extern __shared__ __align__(16) char sm[];
    const uint32_t smb = smem_u32(sm);
    float* part = (float*)(sm + OFF_HB);   // aliases h buffer0-hi

    const int tid = threadIdx.x;
    const int wid = tid >> 5;
    const int lane = tid & 31;
    const int u0 = blockIdx.x * 8;

    const int mt  = wid & 1;
    const int nt2 = (wid >> 1) & 3;
    const int kh  = wid >> 3;
    const int l8 = lane & 7;
    const int asub = lane >> 3;
    const int arow = (asub & 1) * 8 + l8;
    const int akoff = (asub >> 1) * 8;
    const int bkoff = ((lane >> 3) & 1) * 8;
    const int fu = tid & 7;
    const int fb = (tid >> 3) & 31;
    const int lb = tid >> 4;
    const int lj = tid & 15;

    for (int idx = tid; idx < 32 * 256; idx += 512) {
        const int lr = idx >> 8;
        const int kq = idx & 255;
        const int gam = lr >> 3, uu = lr & 7;
        float4 v = __ldg((const float4*)(Whh + (size_t)(gam * HH + u0 + uu) * HH) + kq);
        float hx = __bfloat162float(__float2bfloat16(v.x));
        float hy = __bfloat162float(__float2bfloat16(v.y));
        float hz = __bfloat162float(__float2bfloat16(v.z));
        float hw = __bfloat162float(__float2bfloat16(v.w));
        uint2 hi, lo;
        hi.x = pack_bf2(v.x, v.y);
        hi.y = pack_bf2(v.z, v.w);
        lo.x = pack_bf2(v.x - hx, v.y - hy);
        lo.y = pack_bf2(v.z - hz, v.w - hw);
        const uint32_t off = (uint32_t)(lr * GPW + kq * 4) * 2;
        *(uint2*)(sm + off) = hi;
        *(uint2*)(sm + OFF_WLO + off) = lo;
    }
    float c = (c0 != nullptr) ? c0[fb * HH + u0 + fu] : 0.f;
    __syncthreads();

    float hlast = 0.f;
    for (int t = 0; t < SQ; ++t) {
        const float* hp = (t == 0) ? h0 : (out + (size_t)(t - 1) * BB * HH);
        float a0 = 0.f, a1 = 0.f, a2 = 0.f, a3 = 0.f;
        if (tid < 256) {
            const float* gb = Gin + ((size_t)t * BB + fb) * GG + u0 + fu;
            a0 = __ldcg(gb);
            a1 = __ldcg(gb + HH);
            a2 = __ldcg(gb + 2 * HH);
            a3 = __ldcg(gb + 3 * HH);
        }
        if (hp != nullptr) {
            float acc[4];
            acc[0] = acc[1] = acc[2] = acc[3] = 0.f;

            float4 r[4];
            const float4* hrow = (const float4*)(hp + (size_t)lb * HH);
#pragma unroll
            for (int m = 0; m < 4; ++m) r[m] = __ldcg(hrow + lj + 16 * m);

            for (int cI = 0; cI < 4; ++cI) {
                char* bh = sm + OFF_HB + (size_t)((cI & 1) * 2 + 0) * HBUF_SZ;
                char* bl = sm + OFF_HB + (size_t)((cI & 1) * 2 + 1) * HBUF_SZ;
#pragma unroll
                for (int m = 0; m < 4; ++m) {
                    const int k = (lj + 16 * m) * 4;
                    float hx = __bfloat162float(__float2bfloat16(r[m].x));
                    float hy = __bfloat162float(__float2bfloat16(r[m].y));
                    float hz = __bfloat162float(__float2bfloat16(r[m].z));
                    float hw = __bfloat162float(__float2bfloat16(r[m].w));
                    uint2 hi, lo;
                    hi.x = pack_bf2(r[m].x, r[m].y);
                    hi.y = pack_bf2(r[m].z, r[m].w);
                    lo.x = pack_bf2(r[m].x - hx, r[m].y - hy);
                    lo.y = pack_bf2(r[m].z - hz, r[m].w - hw);
                    *(uint2*)(bh + lb * 528 + k * 2) = hi;
                    *(uint2*)(bl + lb * 528 + k * 2) = lo;
                }
                __syncthreads();
                if (cI < 3) {
#pragma unroll
                    for (int m = 0; m < 4; ++m)
                        r[m] = __ldcg(hrow + (cI + 1) * 64 + lj + 16 * m);
                }
                const uint32_t hhiB = smb + OFF_HB + (uint32_t)((cI & 1) * 2) * HBUF_SZ;
                const uint32_t hloB = hhiB + HBUF_SZ;
#pragma unroll
                for (int ks = 0; ks < 8; ++ks) {
                    const int kg = cI * 256 + kh * 128 + ks * 16;
                    const int kc = kh * 128 + ks * 16;
                    uint32_t ahi[4], alo[4], bhi[2], blo[2];
                    const uint32_t aoff = (uint32_t)((mt * 16 + arow) * GPW + kg + akoff) * 2;
                    ldsm_x4(ahi, smb + aoff);
                    ldsm_x4(alo, smb + OFF_WLO + aoff);
                    const uint32_t boff = (uint32_t)((nt2 * 8 + l8) * HP2 + kc + bkoff) * 2;
                    ldsm_x2(bhi, hhiB + boff);
                    ldsm_x2(blo, hloB + boff);
                    mma_bf16(acc, ahi, bhi);
                    mma_bf16(acc, ahi, blo);
                    mma_bf16(acc, alo, bhi);
                }
            }
            {
                const int g = lane >> 2;
                const int t2 = (lane & 3) * 2;
                const int row0 = mt * 16 + g;
                const int col = nt2 * 8 + t2;
                part[(kh * 32 + row0) * 33 + col]     = acc[0];
                part[(kh * 32 + row0) * 33 + col + 1] = acc[1];
                part[(kh * 32 + row0 + 8) * 33 + col]     = acc[2];
                part[(kh * 32 + row0 + 8) * 33 + col + 1] = acc[3];
            }
        }
        __syncthreads();
        if (tid < 256) {
            if (hp != nullptr) {
#pragma unroll
                for (int kp = 0; kp < 2; ++kp) {
                    const float* pp = part + (size_t)kp * 32 * 33 + fb;
                    a0 += pp[(0 * 8 + fu) * 33];
                    a1 += pp[(1 * 8 + fu) * 33];
                    a2 += pp[(2 * 8 + fu) * 33];
                    a3 += pp[(3 * 8 + fu) * 33];
                }
            }
            float iv = 1.f / (1.f + expf(-a0));
            float fv = 1.f / (1.f + expf(-a1));
            float gv = tanhf(a2);
            float ov = 1.f / (1.f + expf(-a3));
            c = fv * c + iv * gv;
            float hv = ov * tanhf(c);
            __stcg(out + (size_t)t * BB * HH + (size_t)fb * HH + u0 + fu, hv);
            hlast = hv;
        }
        if (t != SQ - 1) grid_barrier(flag_base + (unsigned)t + 1u);
    }
    if (tid < 256) {
        if (hT != nullptr) hT[fb * HH + u0 + fu] = hlast;
        if (cT != nullptr) cT[fb * HH + u0 + fu] = c;
    }
}

// ------------------------- launch --------------------------------------------
extern "C" void kernel_launch(void* const* d_in, const int* in_sizes, int n_in,
                              void* d_out, int out_size) {
    const int*   x       = (const int*)d_in[0];
    const float* emb_enc = (const float*)d_in[1];
    const float* enc_Wih = (const float*)d_in[2];
    const float* enc_Whh = (const float*)d_in[3];
    const float* enc_b   = (const float*)d_in[4];
    const float* emb_dec = (const float*)d_in[5];
    const float* dec_Wih = (const float*)d_in[6];
    const float* dec_Whh = (const float*)d_in[7];
    const float* dec_b   = (const float*)d_in[8];
    float* out = (float*)d_out;

    float *seqA, *seqB, *seqC, *G, *hT, *cT;
    __nv_bfloat16 *Ahi, *Alo, *Whi, *Wlo;
    cudaGetSymbolAddress((void**)&seqA, g_seqA);
    cudaGetSymbolAddress((void**)&seqB, g_seqB);
    cudaGetSymbolAddress((void**)&seqC, g_seqC);
    cudaGetSymbolAddress((void**)&G,    g_G);
    cudaGetSymbolAddress((void**)&hT,   g_hT);
    cudaGetSymbolAddress((void**)&cT,   g_cT);
    cudaGetSymbolAddress((void**)&Ahi,  g_Ahi);
    cudaGetSymbolAddress((void**)&Alo,  g_Alo);
    cudaGetSymbolAddress((void**)&Whi,  g_Whi);
    cudaGetSymbolAddress((void**)&Wlo,  g_Wlo);

    cudaFuncSetAttribute(recur_mma_kernel,
                         cudaFuncAttributeMaxDynamicSharedMemorySize, RECUR_SMEM);

    dim3 tc_grid(GG / 128, MM / 128);  // (32, 128)

    gather_kernel<<<2048, 256>>>(x, emb_enc, seqA);
    gather_kernel<<<2048, 256>>>(x, emb_dec, seqC);

    unsigned launch_idx = 0;

    // ---------------- encoder ----------------
    float* cur = seqA;
    float* nxt = seqB;
    for (int l = 0; l < LL; ++l) {
        cvt_kernel<<<2048, 256>>>(cur, Ahi, Alo, MM * HH / 4);
        cvt_kernel<<<1024, 256>>>(enc_Wih + (size_t)l * GG * HH, Whi, Wlo, GG * HH / 4);
        igemm_mma_kernel<<<tc_grid, 256>>>(Ahi, Alo, Whi, Wlo,
                                           enc_b + (size_t)l * GG, G);
        recur_mma_kernel<<<NBLK, 512, RECUR_SMEM>>>(
            G, enc_Whh + (size_t)l * GG * HH, nullptr, nullptr,
            nxt, hT + (size_t)l * BB * HH, cT + (size_t)l * BB * HH,
            launch_idx * 1024u);
        ++launch_idx;
        float* tmp = cur; cur = nxt; nxt = tmp;
    }

    // ---------------- decoder ----------------
    cur = seqC; nxt = seqA;
    for (int l = 0; l < LL; ++l) {
        cvt_kernel<<<2048, 256>>>(cur, Ahi, Alo, MM * HH / 4);
        cvt_kernel<<<1024, 256>>>(dec_Wih + (size_t)l * GG * HH, Whi, Wlo, GG * HH / 4);
        igemm_mma_kernel<<<tc_grid, 256>>>(Ahi, Alo, Whi, Wlo,
                                           dec_b + (size_t)l * GG, G);
        float* target = (l == LL - 1) ? out : nxt;
        recur_mma_kernel<<<NBLK, 512, RECUR_SMEM>>>(
            G, dec_Whh + (size_t)l * GG * HH,
            hT + (size_t)l * BB * HH, cT + (size_t)l * BB * HH,
            target, nullptr, nullptr,
            launch_idx * 1024u);
        ++launch_idx;
        nxt = cur; cur = target;
    }

    reset_flags_kernel<<<1, 128>>>();
}

// round 15
// speedup vs baseline: 1.2466x; 1.2466x over previous
#include <cuda_runtime.h>
#include <cuda_bf16.h>
#include <cstdint>

// Problem constants
#define SQ 512
#define BB 32
#define HH 1024
#define GG 4096
#define LL 3
#define MM (SQ*BB)
#define NBLK 128

typedef unsigned long long ull;

// ------------------------- scratch (device globals) --------------------------
__device__ float g_seqA[(size_t)MM * HH];
__device__ float g_seqB[(size_t)MM * HH];
__device__ float g_seqC[(size_t)MM * HH];
__device__ float g_G[(size_t)MM * GG];
__device__ float g_hT[LL * BB * HH];
__device__ float g_cT[LL * BB * HH];
__device__ unsigned g_flags[NBLK];
__device__ __nv_bfloat16 g_Ahi[(size_t)MM * HH];
__device__ __nv_bfloat16 g_Alo[(size_t)MM * HH];
__device__ __nv_bfloat16 g_Whi[(size_t)GG * HH];
__device__ __nv_bfloat16 g_Wlo[(size_t)GG * HH];

// ------------------------- grid barrier (R10 verbatim) ------------------------
__device__ __forceinline__ void grid_barrier(unsigned target) {
    __syncthreads();
    const int tid = threadIdx.x;
    if (tid < 32) {
        if (tid == 0) {
            asm volatile("st.release.gpu.global.u32 [%0], %1;"
                         :: "l"(&g_flags[blockIdx.x]), "r"(target) : "memory");
        }
        const unsigned* f = g_flags;
        for (;;) {
            unsigned v0, v1, v2, v3;
            asm volatile("ld.acquire.gpu.global.u32 %0, [%1];" : "=r"(v0) : "l"(f + tid));
            asm volatile("ld.acquire.gpu.global.u32 %0, [%1];" : "=r"(v1) : "l"(f + tid + 32));
            asm volatile("ld.acquire.gpu.global.u32 %0, [%1];" : "=r"(v2) : "l"(f + tid + 64));
            asm volatile("ld.acquire.gpu.global.u32 %0, [%1];" : "=r"(v3) : "l"(f + tid + 96));
            bool ok = (v0 >= target) & (v1 >= target) & (v2 >= target) & (v3 >= target);
            if (__all_sync(0xffffffffu, ok)) break;
        }
    }
    __syncthreads();
}

__global__ void reset_flags_kernel() {
    if (threadIdx.x < NBLK) g_flags[threadIdx.x] = 0u;
}

// ---- bf16 split helpers -------------------------------------------------------
__device__ __forceinline__ uint32_t pack_bf2(float a, float b) {
    __nv_bfloat16 x = __float2bfloat16(a);
    __nv_bfloat16 y = __float2bfloat16(b);
    return (uint32_t)(*(unsigned short*)&x) | ((uint32_t)(*(unsigned short*)&y) << 16);
}
__device__ __forceinline__ void split4(float4 v, ushort4& hp, ushort4& lp) {
    __nv_bfloat16 h0 = __float2bfloat16(v.x);
    __nv_bfloat16 h1 = __float2bfloat16(v.y);
    __nv_bfloat16 h2 = __float2bfloat16(v.z);
    __nv_bfloat16 h3 = __float2bfloat16(v.w);
    __nv_bfloat16 l0 = __float2bfloat16(v.x - __bfloat162float(h0));
    __nv_bfloat16 l1 = __float2bfloat16(v.y - __bfloat162float(h1));
    __nv_bfloat16 l2 = __float2bfloat16(v.z - __bfloat162float(h2));
    __nv_bfloat16 l3 = __float2bfloat16(v.w - __bfloat162float(h3));
    hp.x = *(unsigned short*)&h0; hp.y = *(unsigned short*)&h1;
    hp.z = *(unsigned short*)&h2; hp.w = *(unsigned short*)&h3;
    lp.x = *(unsigned short*)&l0; lp.y = *(unsigned short*)&l1;
    lp.z = *(unsigned short*)&l2; lp.w = *(unsigned short*)&l3;
}

// ------------------------- fused gather + bf16 split (layer 0 inputs) ---------
__global__ void gather_split_kernel(const int* __restrict__ x,
                                    const float* __restrict__ emb,
                                    __nv_bfloat16* __restrict__ hi,
                                    __nv_bfloat16* __restrict__ lo) {
    const int total = MM * (HH / 4);
    for (int i = blockIdx.x * blockDim.x + threadIdx.x; i < total;
         i += gridDim.x * blockDim.x) {
        int row = i >> 8;
        int col = i & 255;
        int tok = __ldg(x + row);
        float4 v = __ldg(((const float4*)(emb + (size_t)tok * HH)) + col);
        ushort4 hp, lp;
        split4(v, hp, lp);
        ((ushort4*)hi)[i] = hp;
        ((ushort4*)lo)[i] = lp;
    }
}

// ------------------------- fp32 -> bf16 hi/lo split ---------------------------
__global__ void cvt_kernel(const float* __restrict__ in,
                           __nv_bfloat16* __restrict__ hi,
                           __nv_bfloat16* __restrict__ lo, int n4) {
    for (int i = blockIdx.x * blockDim.x + threadIdx.x; i < n4;
         i += gridDim.x * blockDim.x) {
        float4 v = __ldcg(((const float4*)in) + i);
        ushort4 hp, lp;
        split4(v, hp, lp);
        ((ushort4*)hi)[i] = hp;
        ((ushort4*)lo)[i] = lp;
    }
}

// ------------------------- mma.sync helpers -----------------------------------
__device__ __forceinline__ uint32_t smem_u32(const void* p) {
    uint32_t a;
    asm("{ .reg .u64 t; cvta.to.shared.u64 t, %1; cvt.u32.u64 %0, t; }"
        : "=r"(a) : "l"(p));
    return a;
}
__device__ __forceinline__ void ldsm_x4(uint32_t* r, uint32_t addr) {
    asm volatile("ldmatrix.sync.aligned.m8n8.x4.shared.b16 {%0,%1,%2,%3}, [%4];"
                 : "=r"(r[0]), "=r"(r[1]), "=r"(r[2]), "=r"(r[3]) : "r"(addr));
}
__device__ __forceinline__ void ldsm_x2(uint32_t* r, uint32_t addr) {
    asm volatile("ldmatrix.sync.aligned.m8n8.x2.shared.b16 {%0,%1}, [%2];"
                 : "=r"(r[0]), "=r"(r[1]) : "r"(addr));
}
__device__ __forceinline__ void mma_bf16(float* d, const uint32_t* a,
                                         const uint32_t* b) {
    asm volatile(
        "mma.sync.aligned.m16n8k16.row.col.f32.bf16.bf16.f32 "
        "{%0,%1,%2,%3}, {%4,%5,%6,%7}, {%8,%9}, {%0,%1,%2,%3};"
        : "+f"(d[0]), "+f"(d[1]), "+f"(d[2]), "+f"(d[3])
        : "r"(a[0]), "r"(a[1]), "r"(a[2]), "r"(a[3]), "r"(b[0]), "r"(b[1]));
}
__device__ __forceinline__ void cp16(uint32_t smaddr, const void* gaddr) {
    asm volatile("cp.async.cg.shared.global [%0], [%1], 16;"
                 :: "r"(smaddr), "l"(gaddr));
}

// ------------------------- tensor-core input GEMM (R10 verbatim) --------------
#define GP 40
__global__ __launch_bounds__(256, 2) void igemm_mma_kernel(
    const __nv_bfloat16* __restrict__ Ahi,
    const __nv_bfloat16* __restrict__ Alo,
    const __nv_bfloat16* __restrict__ Whi,
    const __nv_bfloat16* __restrict__ Wlo,
    const float* __restrict__ bias,
    float* __restrict__ C) {
    __shared__ __align__(16) __nv_bfloat16 sAhi[128 * GP];
    __shared__ __align__(16) __nv_bfloat16 sAlo[128 * GP];
    __shared__ __align__(16) __nv_bfloat16 sWhi[128 * GP];
    __shared__ __align__(16) __nv_bfloat16 sWlo[128 * GP];

    const int tid = threadIdx.x;
    const int wid = tid >> 5;
    const int lane = tid & 31;
    const int bm = blockIdx.y * 128;
    const int bn = blockIdx.x * 128;
    const int wm = wid & 3;
    const int wn = wid >> 2;

    float acc[2][8][4];
#pragma unroll
    for (int mt = 0; mt < 2; ++mt)
#pragma unroll
        for (int nt = 0; nt < 8; ++nt)
#pragma unroll
            for (int q = 0; q < 4; ++q) acc[mt][nt][q] = 0.f;

    const int lrow0 = tid >> 2;
    const int lq = tid & 3;
    const int l8 = lane & 7;
    const int asub = lane >> 3;
    const int arow = (asub & 1) * 8 + l8;
    const int akoff = (asub >> 1) * 8;
    const int bkoff = ((lane >> 3) & 1) * 8;

    const uint32_t sAhiB = smem_u32(sAhi);
    const uint32_t sAloB = smem_u32(sAlo);
    const uint32_t sWhiB = smem_u32(sWhi);
    const uint32_t sWloB = smem_u32(sWlo);

    for (int c = 0; c < 32; ++c) {
        if (c) __syncthreads();
        const int k0 = c * 32;
#pragma unroll
        for (int j = 0; j < 2; ++j) {
            const int row = lrow0 + j * 64;
            const uint32_t so = (uint32_t)(row * GP + lq * 8) * 2;
            const size_t ga = (size_t)(bm + row) * HH + k0 + lq * 8;
            const size_t gw = (size_t)(bn + row) * HH + k0 + lq * 8;
            cp16(sAhiB + so, Ahi + ga);
            cp16(sAloB + so, Alo + ga);
            cp16(sWhiB + so, Whi + gw);
            cp16(sWloB + so, Wlo + gw);
        }
        asm volatile("cp.async.commit_group;");
        asm volatile("cp.async.wait_group 0;" ::: "memory");
        __syncthreads();
#pragma unroll
        for (int term = 0; term < 3; ++term) {
            const uint32_t Asb = (term == 2) ? sAloB : sAhiB;
            const uint32_t Wsb = (term == 1) ? sWloB : sWhiB;
#pragma unroll
            for (int ks = 0; ks < 2; ++ks) {
                uint32_t a[2][4];
#pragma unroll
                for (int mt = 0; mt < 2; ++mt) {
                    const uint32_t aaddr = Asb
                        + ((uint32_t)((wm * 32 + mt * 16 + arow) * GP
                                      + ks * 16 + akoff)) * 2;
                    ldsm_x4(a[mt], aaddr);
                }
#pragma unroll
                for (int nt = 0; nt < 8; ++nt) {
                    uint32_t b[2];
                    const uint32_t baddr = Wsb
                        + ((uint32_t)((wn * 64 + nt * 8 + l8) * GP
                                      + ks * 16 + bkoff)) * 2;
                    ldsm_x2(b, baddr);
                    mma_bf16(acc[0][nt], a[0], b);
                    mma_bf16(acc[1][nt], a[1], b);
                }
            }
        }
    }

    const int g = lane >> 2;
    const int t2 = (lane & 3) * 2;
#pragma unroll
    for (int nt = 0; nt < 8; ++nt) {
        const int n = bn + wn * 64 + nt * 8 + t2;
        const float2 bv = *(const float2*)(bias + n);
#pragma unroll
        for (int mt = 0; mt < 2; ++mt) {
            const int m0 = bm + wm * 32 + mt * 16 + g;
            float2 o0, o1;
            o0.x = acc[mt][nt][0] + bv.x;
            o0.y = acc[mt][nt][1] + bv.y;
            o1.x = acc[mt][nt][2] + bv.x;
            o1.y = acc[mt][nt][3] + bv.y;
            *(float2*)(C + (size_t)m0 * GG + n) = o0;
            *(float2*)(C + (size_t)(m0 + 8) * GG + n) = o1;
        }
    }
}

// ------------------------- tensor-core persistent recurrence (R10 verbatim) ---
#define GPW 1032
#define HP2 264
#define OFF_WLO 66048
#define OFF_HB  132096
#define HBUF_SZ 16896
#define RECUR_SMEM 199680
__global__ __launch_bounds__(512, 1) void recur_mma_kernel(
    const float* __restrict__ Gin,   // [SQ*BB][GG] natural
    const float* __restrict__ Whh,   // [GG, HH]
    const float* __restrict__ h0,
    const float* __restrict__ c0,
    float* __restrict__ out,         // [SQ,BB,HH]
    float* __restrict__ hT,
    float* __restrict__ cT,
    unsigned flag_base) {
    extern __shared__ __align__(16) char sm[];
    const uint32_t smb = smem_u32(sm);
    float* part = (float*)(sm + OFF_HB);   // aliases h buffer0-hi

    const int tid = threadIdx.x;
    const int wid = tid >> 5;
    const int lane = tid & 31;
    const int u0 = blockIdx.x * 8;

    const int mt  = wid & 1;
    const int nt2 = (wid >> 1) & 3;
    const int kh  = wid >> 3;
    const int l8 = lane & 7;
    const int asub = lane >> 3;
    const int arow = (asub & 1) * 8 + l8;
    const int akoff = (asub >> 1) * 8;
    const int bkoff = ((lane >> 3) & 1) * 8;
    const int fu = tid & 7;
    const int fb = (tid >> 3) & 31;
    const int lb = tid >> 4;
    const int lj = tid & 15;

    for (int idx = tid; idx < 32 * 256; idx += 512) {
        const int lr = idx >> 8;
        const int kq = idx & 255;
        const int gam = lr >> 3, uu = lr & 7;
        float4 v = __ldg((const float4*)(Whh + (size_t)(gam * HH + u0 + uu) * HH) + kq);
        float hx = __bfloat162float(__float2bfloat16(v.x));
        float hy = __bfloat162float(__float2bfloat16(v.y));
        float hz = __bfloat162float(__float2bfloat16(v.z));
        float hw = __bfloat162float(__float2bfloat16(v.w));
        uint2 hi, lo;
        hi.x = pack_bf2(v.x, v.y);
        hi.y = pack_bf2(v.z, v.w);
        lo.x = pack_bf2(v.x - hx, v.y - hy);
        lo.y = pack_bf2(v.z - hz, v.w - hw);
        const uint32_t off = (uint32_t)(lr * GPW + kq * 4) * 2;
        *(uint2*)(sm + off) = hi;
        *(uint2*)(sm + OFF_WLO + off) = lo;
    }
    float c = (c0 != nullptr) ? c0[fb * HH + u0 + fu] : 0.f;
    __syncthreads();

    float hlast = 0.f;
    for (int t = 0; t < SQ; ++t) {
        const float* hp = (t == 0) ? h0 : (out + (size_t)(t - 1) * BB * HH);
        float a0 = 0.f, a1 = 0.f, a2 = 0.f, a3 = 0.f;
        if (tid < 256) {
            const float* gb = Gin + ((size_t)t * BB + fb) * GG + u0 + fu;
            a0 = __ldcg(gb);
            a1 = __ldcg(gb + HH);
            a2 = __ldcg(gb + 2 * HH);
            a3 = __ldcg(gb + 3 * HH);
        }
        if (hp != nullptr) {
            float acc[4];
            acc[0] = acc[1] = acc[2] = acc[3] = 0.f;

            float4 r[4];
            const float4* hrow = (const float4*)(hp + (size_t)lb * HH);
#pragma unroll
            for (int m = 0; m < 4; ++m) r[m] = __ldcg(hrow + lj + 16 * m);

            for (int cI = 0; cI < 4; ++cI) {
                char* bh = sm + OFF_HB + (size_t)((cI & 1) * 2 + 0) * HBUF_SZ;
                char* bl = sm + OFF_HB + (size_t)((cI & 1) * 2 + 1) * HBUF_SZ;
#pragma unroll
                for (int m = 0; m < 4; ++m) {
                    const int k = (lj + 16 * m) * 4;
                    float hx = __bfloat162float(__float2bfloat16(r[m].x));
                    float hy = __bfloat162float(__float2bfloat16(r[m].y));
                    float hz = __bfloat162float(__float2bfloat16(r[m].z));
                    float hw = __bfloat162float(__float2bfloat16(r[m].w));
                    uint2 hi, lo;
                    hi.x = pack_bf2(r[m].x, r[m].y);
                    hi.y = pack_bf2(r[m].z, r[m].w);
                    lo.x = pack_bf2(r[m].x - hx, r[m].y - hy);
                    lo.y = pack_bf2(r[m].z - hz, r[m].w - hw);
                    *(uint2*)(bh + lb * 528 + k * 2) = hi;
                    *(uint2*)(bl + lb * 528 + k * 2) = lo;
                }
                __syncthreads();
                if (cI < 3) {
#pragma unroll
                    for (int m = 0; m < 4; ++m)
                        r[m] = __ldcg(hrow + (cI + 1) * 64 + lj + 16 * m);
                }
                const uint32_t hhiB = smb + OFF_HB + (uint32_t)((cI & 1) * 2) * HBUF_SZ;
                const uint32_t hloB = hhiB + HBUF_SZ;
#pragma unroll
                for (int ks = 0; ks < 8; ++ks) {
                    const int kg = cI * 256 + kh * 128 + ks * 16;
                    const int kc = kh * 128 + ks * 16;
                    uint32_t ahi[4], alo[4], bhi[2], blo[2];
                    const uint32_t aoff = (uint32_t)((mt * 16 + arow) * GPW + kg + akoff) * 2;
                    ldsm_x4(ahi, smb + aoff);
                    ldsm_x4(alo, smb + OFF_WLO + aoff);
                    const uint32_t boff = (uint32_t)((nt2 * 8 + l8) * HP2 + kc + bkoff) * 2;
                    ldsm_x2(bhi, hhiB + boff);
                    ldsm_x2(blo, hloB + boff);
                    mma_bf16(acc, ahi, bhi);
                    mma_bf16(acc, ahi, blo);
                    mma_bf16(acc, alo, bhi);
                }
            }
            {
                const int g = lane >> 2;
                const int t2 = (lane & 3) * 2;
                const int row0 = mt * 16 + g;
                const int col = nt2 * 8 + t2;
                part[(kh * 32 + row0) * 33 + col]     = acc[0];
                part[(kh * 32 + row0) * 33 + col + 1] = acc[1];
                part[(kh * 32 + row0 + 8) * 33 + col]     = acc[2];
                part[(kh * 32 + row0 + 8) * 33 + col + 1] = acc[3];
            }
        }
        __syncthreads();
        if (tid < 256) {
            if (hp != nullptr) {
#pragma unroll
                for (int kp = 0; kp < 2; ++kp) {
                    const float* pp = part + (size_t)kp * 32 * 33 + fb;
                    a0 += pp[(0 * 8 + fu) * 33];
                    a1 += pp[(1 * 8 + fu) * 33];
                    a2 += pp[(2 * 8 + fu) * 33];
                    a3 += pp[(3 * 8 + fu) * 33];
                }
            }
            float iv = 1.f / (1.f + expf(-a0));
            float fv = 1.f / (1.f + expf(-a1));
            float gv = tanhf(a2);
            float ov = 1.f / (1.f + expf(-a3));
            c = fv * c + iv * gv;
            float hv = ov * tanhf(c);
            __stcg(out + (size_t)t * BB * HH + (size_t)fb * HH + u0 + fu, hv);
            hlast = hv;
        }
        if (t != SQ - 1) grid_barrier(flag_base + (unsigned)t + 1u);
    }
    if (tid < 256) {
        if (hT != nullptr) hT[fb * HH + u0 + fu] = hlast;
        if (cT != nullptr) cT[fb * HH + u0 + fu] = c;
    }
}

// ------------------------- launch --------------------------------------------
extern "C" void kernel_launch(void* const* d_in, const int* in_sizes, int n_in,
                              void* d_out, int out_size) {
    const int*   x       = (const int*)d_in[0];
    const float* emb_enc = (const float*)d_in[1];
    const float* enc_Wih = (const float*)d_in[2];
    const float* enc_Whh = (const float*)d_in[3];
    const float* enc_b   = (const float*)d_in[4];
    const float* emb_dec = (const float*)d_in[5];
    const float* dec_Wih = (const float*)d_in[6];
    const float* dec_Whh = (const float*)d_in[7];
    const float* dec_b   = (const float*)d_in[8];
    float* out = (float*)d_out;

    float *seqA, *seqB, *seqC, *G, *hT, *cT;
    __nv_bfloat16 *Ahi, *Alo, *Whi, *Wlo;
    cudaGetSymbolAddress((void**)&seqA, g_seqA);
    cudaGetSymbolAddress((void**)&seqB, g_seqB);
    cudaGetSymbolAddress((void**)&seqC, g_seqC);
    cudaGetSymbolAddress((void**)&G,    g_G);
    cudaGetSymbolAddress((void**)&hT,   g_hT);
    cudaGetSymbolAddress((void**)&cT,   g_cT);
    cudaGetSymbolAddress((void**)&Ahi,  g_Ahi);
    cudaGetSymbolAddress((void**)&Alo,  g_Alo);
    cudaGetSymbolAddress((void**)&Whi,  g_Whi);
    cudaGetSymbolAddress((void**)&Wlo,  g_Wlo);

    cudaFuncSetAttribute(recur_mma_kernel,
                         cudaFuncAttributeMaxDynamicSharedMemorySize, RECUR_SMEM);

    dim3 tc_grid(GG / 128, MM / 128);  // (32, 128)

    unsigned launch_idx = 0;

    // ---------------- encoder ----------------
    // layer 0 input: fused gather+split straight into Ahi/Alo
    float* cur = nullptr;
    float* nxt = seqB;
    for (int l = 0; l < LL; ++l) {
        if (l == 0) {
            gather_split_kernel<<<2048, 256>>>(x, emb_enc, Ahi, Alo);
        } else {
            cvt_kernel<<<2048, 256>>>(cur, Ahi, Alo, MM * HH / 4);
        }
        cvt_kernel<<<1024, 256>>>(enc_Wih + (size_t)l * GG * HH, Whi, Wlo, GG * HH / 4);
        igemm_mma_kernel<<<tc_grid, 256>>>(Ahi, Alo, Whi, Wlo,
                                           enc_b + (size_t)l * GG, G);
        recur_mma_kernel<<<NBLK, 512, RECUR_SMEM>>>(
            G, enc_Whh + (size_t)l * GG * HH, nullptr, nullptr,
            nxt, hT + (size_t)l * BB * HH, cT + (size_t)l * BB * HH,
            launch_idx * 1024u);
        ++launch_idx;
        cur = nxt;
        nxt = (nxt == seqB) ? seqA : seqB;
    }

    // ---------------- decoder ----------------
    cur = nullptr;
    nxt = seqA;
    for (int l = 0; l < LL; ++l) {
        if (l == 0) {
            gather_split_kernel<<<2048, 256>>>(x, emb_dec, Ahi, Alo);
        } else {
            cvt_kernel<<<2048, 256>>>(cur, Ahi, Alo, MM * HH / 4);
        }
        cvt_kernel<<<1024, 256>>>(dec_Wih + (size_t)l * GG * HH, Whi, Wlo, GG * HH / 4);
        igemm_mma_kernel<<<tc_grid, 256>>>(Ahi, Alo, Whi, Wlo,
                                           dec_b + (size_t)l * GG, G);
        float* target = (l == LL - 1) ? out : nxt;
        recur_mma_kernel<<<NBLK, 512, RECUR_SMEM>>>(
            G, dec_Whh + (size_t)l * GG * HH,
            hT + (size_t)l * BB * HH, cT + (size_t)l * BB * HH,
            target, nullptr, nullptr,
            launch_idx * 1024u);
        ++launch_idx;
        cur = target;
        nxt = (nxt == seqA) ? seqC : seqA;
    }

    reset_flags_kernel<<<1, 128>>>();
}